// round 14
// baseline (speedup 1.0000x reference)
#include <cuda_runtime.h>
#include <cuda_fp16.h>
#include <cstdint>
#include <math.h>

#define NB      2
#define LQ      12240
#define DIM     256
#define HEADS   8
#define LEVELS  4
#define POINTS  4
#define HD      32
#define MROWS   (NB * LQ)   // 24480

#define VN      (HEADS * MROWS * HD)   // elements per value plane
#define VPLANE  (VN + 32)              // plane1 offset (+32 elem = +64B shift)

// ------------------------- scratch (no allocs allowed) ----------------------
// value, HEAD-MAJOR [head][row][32ch] fp16, TWO parity planes:
// plane0 at [0], plane1 (same data shifted +32 elems) at [VPLANE].
__device__ __align__(128) __half g_value2[2 * VN + 64];
__device__ float  g_off    [MROWS * DIM];
__device__ float  g_attn   [MROWS * HEADS * 16];
__device__ float  g_out2   [MROWS * DIM];

// fp16 A operand (src, then attention output) and concatenated transposed
// weights [n][k] K-major: rows 0-255 value, 256-511 off, 512-639 attn, 640-895 out
__device__ __half g_af [MROWS * DIM];
__device__ __half g_btc[896 * 256];

// ------------------------------ PTX helpers ---------------------------------
__device__ __forceinline__ uint32_t smem_u32(const void* p) {
    uint32_t a;
    asm("{ .reg .u64 t; cvta.to.shared.u64 t, %1; cvt.u32.u64 %0, t; }" : "=r"(a) : "l"(p));
    return a;
}
__device__ __forceinline__ void cpa16(uint32_t dst, const void* src, bool v) {
    asm volatile("cp.async.cg.shared.global [%0], [%1], 16, %2;"
        :: "r"(dst), "l"(src), "r"(v ? 16 : 0) : "memory");
}
__device__ __forceinline__ void ldsm_x4(uint32_t addr, uint32_t* r) {
    asm volatile("ldmatrix.sync.aligned.m8n8.x4.shared.b16 {%0,%1,%2,%3}, [%4];"
        : "=r"(r[0]), "=r"(r[1]), "=r"(r[2]), "=r"(r[3]) : "r"(addr));
}
__device__ __forceinline__ void mma_f16(float* c, const uint32_t* a, const uint32_t* b) {
    asm volatile("mma.sync.aligned.m16n8k16.row.col.f32.f16.f16.f32 "
        "{%0,%1,%2,%3}, {%4,%5,%6,%7}, {%8,%9}, {%0,%1,%2,%3};"
        : "+f"(c[0]), "+f"(c[1]), "+f"(c[2]), "+f"(c[3])
        : "r"(a[0]), "r"(a[1]), "r"(a[2]), "r"(a[3]), "r"(b[0]), "r"(b[1]));
}

// ---------------------------------------------------------------------------
// Fused split kernel:
//  blocks [0,224): 32x32 smem-tile transpose of the 4 weight matrices -> fp16
//  blocks [224,...): src fp32 -> fp16 (vectorized)
// ---------------------------------------------------------------------------
#define WT_TILES 224   // wv 64 | wo 64 | wa 32 | ww 64

__global__ __launch_bounds__(256) void split_all_kernel(
    const float* __restrict__ A, __half* __restrict__ Af, int n4,
    const float* __restrict__ wv, const float* __restrict__ wo,
    const float* __restrict__ wa, const float* __restrict__ ww,
    __half* __restrict__ Bt)
{
    const int bid = blockIdx.x;
    if (bid < WT_TILES) {
        __shared__ float sm[32][33];
        const float* src; int rowoff, Nc, local;
        if (bid < 64)       { src = wv; rowoff = 0;   Nc = 256; local = bid; }
        else if (bid < 128) { src = wo; rowoff = 256; Nc = 256; local = bid - 64; }
        else if (bid < 160) { src = wa; rowoff = 512; Nc = 128; local = bid - 128; }
        else                { src = ww; rowoff = 640; Nc = 256; local = bid - 160; }
        const int ntiles = Nc >> 5;
        const int k0 = (local / ntiles) * 32;
        const int n0 = (local % ntiles) * 32;
        const int tx = threadIdx.x & 31;
        const int ty = threadIdx.x >> 5;   // 0..7
#pragma unroll
        for (int i = 0; i < 4; i++)
            sm[ty + i * 8][tx] = src[(k0 + ty + i * 8) * Nc + n0 + tx];
        __syncthreads();
#pragma unroll
        for (int i = 0; i < 4; i++)
            Bt[(size_t)(rowoff + n0 + ty + i * 8) * 256 + k0 + tx] =
                __float2half_rn(sm[tx][ty + i * 8]);
    } else {
        int i = (bid - WT_TILES) * 256 + threadIdx.x;
        if (i >= n4) return;
        float4 a = ((const float4*)A)[i];
        __half2 p0 = __floats2half2_rn(a.x, a.y);
        __half2 p1 = __floats2half2_rn(a.z, a.w);
        uint2 v;
        v.x = *(uint32_t*)&p0;
        v.y = *(uint32_t*)&p1;
        *(uint2*)(Af + 4 * (size_t)i) = v;
    }
}

// ---------------------------------------------------------------------------
// GEMM1 (fused projections): CTA 128x128, 8 warps 4(M)x2(N), warp 32x64,
// 3-stage cp.async, 2 CTAs/SM. blockIdx.y 0-1 value(fp16 head-major, DUAL
// parity planes), 2-3 off, 4 attn.
// ---------------------------------------------------------------------------
#define PADK 40
#define ST1_BYTES 20480     // A 10240 + B 10240
#define SMEM1_BYTES (3 * ST1_BYTES)

__global__ __launch_bounds__(256, 2) void gemm1_kernel(
    const __half* __restrict__ Af, const __half* __restrict__ Bt,
    __half* C0h, float* C1, float* C2,
    const float* b0, const float* b1, const float* b2, int M)
{
    extern __shared__ __align__(16) char smem[];
    const uint32_t sbase = smem_u32(smem);

    const int tid  = threadIdx.x;
    const int lane = tid & 31;
    const int wid  = tid >> 5;
    const int wm   = wid & 3;
    const int wn   = wid >> 2;
    const int bm   = blockIdx.x * 128;
    const int bn   = blockIdx.y * 128;

    float* Cp; const float* bp; int stride, coloff; bool halfOut = false;
    if (blockIdx.y < 2)      { Cp = nullptr; bp = b0; stride = 256; coloff = bn; halfOut = true; }
    else if (blockIdx.y < 4) { Cp = C1; bp = b1; stride = 256; coloff = bn - 256; }
    else                     { Cp = C2; bp = b2; stride = 128; coloff = 0; }

    float acc[2][8][4];
#pragma unroll
    for (int i = 0; i < 2; i++)
#pragma unroll
        for (int j = 0; j < 8; j++)
#pragma unroll
            for (int t = 0; t < 4; t++) acc[i][j][t] = 0.f;

    auto load_chunk = [&](int kk, int st) {
        const uint32_t base = sbase + st * ST1_BYTES;
#pragma unroll
        for (int t = 0; t < 2; t++) {
            int idx = tid + 256 * t;
            int row = idx >> 2, seg = idx & 3;
            uint32_t d = (uint32_t)(row * PADK + seg * 8) * 2;
            bool va = (bm + row) < M;
            cpa16(base + d, Af + (size_t)(bm + row) * 256 + kk * 32 + seg * 8, va);
            cpa16(base + 10240 + d, Bt + (size_t)(bn + row) * 256 + kk * 32 + seg * 8, true);
        }
        asm volatile("cp.async.commit_group;" ::: "memory");
    };

    load_chunk(0, 0);
    load_chunk(1, 1);

    const int arow = wm * 32 + (lane & 15);
    const int acolbase = (lane >> 4) * 8;
    const int browq = wn * 64 + (lane & 7) + ((lane >> 4) & 1) * 8;
    const int bcolbase = ((lane >> 3) & 1) * 8;

    for (int kk = 0; kk < 8; kk++) {
        asm volatile("cp.async.wait_group 1;" ::: "memory");
        __syncthreads();
        if (kk + 2 < 8) load_chunk(kk + 2, (kk + 2) % 3);

        const uint32_t ab = sbase + (kk % 3) * ST1_BYTES;

        uint32_t Ar[2][2][4];
        uint32_t Br[2][4][4];
#pragma unroll
        for (int ks = 0; ks < 2; ks++) {
#pragma unroll
            for (int mt = 0; mt < 2; mt++) {
                int row = arow + mt * 16;
                int col = ks * 16 + acolbase;
                ldsm_x4(ab + (uint32_t)(row * PADK + col) * 2, Ar[ks][mt]);
            }
#pragma unroll
            for (int q = 0; q < 4; q++) {
                int rowB = browq + q * 16;
                int colB = bcolbase + ks * 16;
                ldsm_x4(ab + 10240 + (uint32_t)(rowB * PADK + colB) * 2, Br[ks][q]);
            }
        }
#pragma unroll
        for (int ks = 0; ks < 2; ks++)
#pragma unroll
            for (int q = 0; q < 4; q++)
#pragma unroll
                for (int mt = 0; mt < 2; mt++) {
                    mma_f16(acc[mt][2 * q + 0], Ar[ks][mt], Br[ks][q] + 0);
                    mma_f16(acc[mt][2 * q + 1], Ar[ks][mt], Br[ks][q] + 2);
                }
    }

#pragma unroll
    for (int mt = 0; mt < 2; mt++) {
        int r0 = bm + wm * 32 + mt * 16 + (lane >> 2);
        int r1 = r0 + 8;
#pragma unroll
        for (int nt = 0; nt < 8; nt++) {
            int c = coloff + wn * 64 + nt * 8 + 2 * (lane & 3);
            float bb0 = bp[c], bb1 = bp[c + 1];
            if (halfOut) {
                const int h = c >> 5, chm = c & 31;
                __half* basep = C0h + (size_t)h * MROWS * HD + chm;
                if (r0 < M) {
                    __half2 v = __floats2half2_rn(acc[mt][nt][0] + bb0, acc[mt][nt][1] + bb1);
                    *(__half2*)(basep + (size_t)r0 * HD) = v;
                    *(__half2*)(basep + (size_t)r0 * HD + VPLANE) = v;   // parity plane1
                }
                if (r1 < M) {
                    __half2 v = __floats2half2_rn(acc[mt][nt][2] + bb0, acc[mt][nt][3] + bb1);
                    *(__half2*)(basep + (size_t)r1 * HD) = v;
                    *(__half2*)(basep + (size_t)r1 * HD + VPLANE) = v;
                }
            } else {
                if (r0 < M) {
                    float2 v = make_float2(acc[mt][nt][0] + bb0, acc[mt][nt][1] + bb1);
                    *(float2*)&Cp[(size_t)r0 * stride + c] = v;
                }
                if (r1 < M) {
                    float2 v = make_float2(acc[mt][nt][2] + bb0, acc[mt][nt][3] + bb1);
                    *(float2*)&Cp[(size_t)r1 * stride + c] = v;
                }
            }
        }
    }
}

// ---------------------------------------------------------------------------
// GEMM2 (output projection): CTA 128x64, 8 warps 4(M)x2(N), warp 32x32,
// 3-stage cp.async, 3 CTAs/SM.
// ---------------------------------------------------------------------------
#define A2_BYTES 10240
#define B2_BYTES 5120
#define ST2_BYTES (A2_BYTES + B2_BYTES)
#define SMEM2_BYTES (3 * ST2_BYTES)

__global__ __launch_bounds__(256, 3) void gemm2_kernel(
    const __half* __restrict__ Af, const __half* __restrict__ Bt,
    float* C, const float* bias, int M)
{
    extern __shared__ __align__(16) char smem[];
    const uint32_t sbase = smem_u32(smem);

    const int tid  = threadIdx.x;
    const int lane = tid & 31;
    const int wid  = tid >> 5;
    const int wm   = wid & 3;
    const int wn   = wid >> 2;
    const int bm   = blockIdx.x * 128;
    const int bn   = blockIdx.y * 64;

    float acc[2][4][4];
#pragma unroll
    for (int i = 0; i < 2; i++)
#pragma unroll
        for (int j = 0; j < 4; j++)
#pragma unroll
            for (int t = 0; t < 4; t++) acc[i][j][t] = 0.f;

    auto load_chunk = [&](int kk, int st) {
        const uint32_t base = sbase + st * ST2_BYTES;
#pragma unroll
        for (int t = 0; t < 2; t++) {
            int idx = tid + 256 * t;
            int row = idx >> 2, seg = idx & 3;
            uint32_t d = (uint32_t)(row * PADK + seg * 8) * 2;
            bool va = (bm + row) < M;
            cpa16(base + d, Af + (size_t)(bm + row) * 256 + kk * 32 + seg * 8, va);
        }
        {
            int row = tid >> 2, seg = tid & 3;
            uint32_t d = (uint32_t)(row * PADK + seg * 8) * 2;
            cpa16(base + A2_BYTES + d, Bt + (size_t)(bn + row) * 256 + kk * 32 + seg * 8, true);
        }
        asm volatile("cp.async.commit_group;" ::: "memory");
    };

    load_chunk(0, 0);
    load_chunk(1, 1);

    const int arow = wm * 32 + (lane & 15);
    const int acolbase = (lane >> 4) * 8;
    const int browq = wn * 32 + (lane & 7) + ((lane >> 4) & 1) * 8;
    const int bcolbase = ((lane >> 3) & 1) * 8;

    for (int kk = 0; kk < 8; kk++) {
        asm volatile("cp.async.wait_group 1;" ::: "memory");
        __syncthreads();
        if (kk + 2 < 8) load_chunk(kk + 2, (kk + 2) % 3);

        const uint32_t ab = sbase + (kk % 3) * ST2_BYTES;

        uint32_t Ar[2][2][4];
        uint32_t Br[2][2][4];
#pragma unroll
        for (int ks = 0; ks < 2; ks++) {
#pragma unroll
            for (int mt = 0; mt < 2; mt++) {
                int row = arow + mt * 16;
                int col = ks * 16 + acolbase;
                ldsm_x4(ab + (uint32_t)(row * PADK + col) * 2, Ar[ks][mt]);
            }
#pragma unroll
            for (int q = 0; q < 2; q++) {
                int rowB = browq + q * 16;
                int colB = bcolbase + ks * 16;
                ldsm_x4(ab + A2_BYTES + (uint32_t)(rowB * PADK + colB) * 2, Br[ks][q]);
            }
        }
#pragma unroll
        for (int ks = 0; ks < 2; ks++)
#pragma unroll
            for (int q = 0; q < 2; q++)
#pragma unroll
                for (int mt = 0; mt < 2; mt++) {
                    mma_f16(acc[mt][2 * q + 0], Ar[ks][mt], Br[ks][q] + 0);
                    mma_f16(acc[mt][2 * q + 1], Ar[ks][mt], Br[ks][q] + 2);
                }
    }

#pragma unroll
    for (int mt = 0; mt < 2; mt++) {
        int r0 = bm + wm * 32 + mt * 16 + (lane >> 2);
        int r1 = r0 + 8;
#pragma unroll
        for (int nt = 0; nt < 4; nt++) {
            int c = bn + wn * 32 + nt * 8 + 2 * (lane & 3);
            float bb0 = bias[c], bb1 = bias[c + 1];
            if (r0 < M) {
                float2 v = make_float2(acc[mt][nt][0] + bb0, acc[mt][nt][1] + bb1);
                *(float2*)&C[(size_t)r0 * 256 + c] = v;
            }
            if (r1 < M) {
                float2 v = make_float2(acc[mt][nt][2] + bb0, acc[mt][nt][3] + bb1);
                *(float2*)&C[(size_t)r1 * 256 + c] = v;
            }
        }
    }
}

// ---------------------------------------------------------------------------
// Deformable sampling: head-major fp16 value, x-pair gathers, DUAL parity
// planes -> every point-row region is exactly one 128B line.
// ---------------------------------------------------------------------------
__global__ __launch_bounds__(256) void sample_kernel(
    const __half* __restrict__ value,
    const float* __restrict__ off,
    const float* __restrict__ logits,
    const float* __restrict__ ref,
    __half* __restrict__ outA)
{
    const unsigned FULL = 0xffffffffu;
    __shared__ float2 s_aw[HEADS * 16 * 4];   // (addr_as_float, weight)

    const int qg  = blockIdx.x;
    const int n   = qg / LQ;
    const int tid = threadIdx.x;

    if (tid < 128) {
        const int h = tid >> 4;
        const int p = tid & 15;
        const int l = p >> 2;

        float lg = logits[(size_t)qg * 128 + h * 16 + p];
        float mx = lg;
#pragma unroll
        for (int o = 8; o > 0; o >>= 1) mx = fmaxf(mx, __shfl_xor_sync(FULL, mx, o));
        float e = __expf(lg - mx);
        float sum = e;
#pragma unroll
        for (int o = 8; o > 0; o >>= 1) sum += __shfl_xor_sync(FULL, sum, o);
        const float aw = __fdividef(e, sum);

        const int W  = 96 >> l;
        const int S0 = 12288 - 3 * (4096 >> (2 * l));
        const float rx = ref[(size_t)qg * (LEVELS * 2) + l * 2 + 0] * (float)W;
        const float ry = ref[(size_t)qg * (LEVELS * 2) + l * 2 + 1] * (float)W;
        const float ox = off[(size_t)qg * DIM + h * 32 + p * 2 + 0];
        const float oy = off[(size_t)qg * DIM + h * 32 + p * 2 + 1];
        const float x = rx + ox - 0.5f;
        const float y = ry + oy - 0.5f;
        const float x0f = floorf(x), y0f = floorf(y);
        const int x0 = (int)x0f, y0 = (int)y0f;
        const int x1 = x0 + 1, y1 = y0 + 1;
        const float fx = x - x0f, fy = y - y0f;

        const float wx0 = (x0 >= 0 && x0 < W) ? (1.f - fx) : 0.f;
        const float wx1 = (x1 >= 0 && x1 < W) ? fx : 0.f;
        const int pb = min(max(x0, 0), W - 2);
        const float wa = (pb == x0) ? wx0 : ((pb == x1) ? wx1 : 0.f);
        const float wb = (pb + 1 == x0) ? wx0 : ((pb + 1 == x1) ? wx1 : 0.f);
        const float wy0 = ((y0 >= 0 && y0 < W) ? (1.f - fy) : 0.f) * aw;
        const float wy1 = ((y1 >= 0 && y1 < W) ? fy : 0.f) * aw;
        const int y0c = min(max(y0, 0), W - 1);
        const int y1c = min(max(y1, 0), W - 1);
        const int psel = (pb & 1) ? VPLANE : 0;   // parity plane select
        const int a0 = (S0 + y0c * W + pb) * HD + psel;
        const int a1 = (S0 + y1c * W + pb) * HD + psel;

        const int b = tid * 4;
        s_aw[b + 0] = make_float2(__int_as_float(a0),      wa * wy0);
        s_aw[b + 1] = make_float2(__int_as_float(a0 + HD), wb * wy0);
        s_aw[b + 2] = make_float2(__int_as_float(a1),      wa * wy1);
        s_aw[b + 3] = make_float2(__int_as_float(a1 + HD), wb * wy1);
    }
    __syncthreads();

    const int h    = tid >> 5;
    const int lane = tid & 31;
    const int slot = lane >> 3;        // (ypair<<1)|xslot
    const int ch   = (lane & 7) * 4;   // channel base 0..28

    const __half* vb = value + ((size_t)h * MROWS + (size_t)n * LQ) * HD + ch;
    float4 acc = make_float4(0.f, 0.f, 0.f, 0.f);
#pragma unroll
    for (int p = 0; p < 16; p++) {
        const float2 t = s_aw[(h * 16 + p) * 4 + slot];
        const int a = __float_as_int(t.x);
        const float w = t.y;
        const uint2 raw = *(const uint2*)(vb + a);
        const float2 v0 = __half22float2(*(const __half2*)&raw.x);
        const float2 v1 = __half22float2(*(const __half2*)&raw.y);
        acc.x = fmaf(w, v0.x, acc.x);
        acc.y = fmaf(w, v0.y, acc.y);
        acc.z = fmaf(w, v1.x, acc.z);
        acc.w = fmaf(w, v1.y, acc.w);
    }
#pragma unroll
    for (int o = 8; o <= 16; o <<= 1) {
        acc.x += __shfl_xor_sync(FULL, acc.x, o);
        acc.y += __shfl_xor_sync(FULL, acc.y, o);
        acc.z += __shfl_xor_sync(FULL, acc.z, o);
        acc.w += __shfl_xor_sync(FULL, acc.w, o);
    }
    if (lane < 8) {
        __half2 p0 = __floats2half2_rn(acc.x, acc.y);
        __half2 p1 = __floats2half2_rn(acc.z, acc.w);
        uint2 v;
        v.x = *(uint32_t*)&p0;
        v.y = *(uint32_t*)&p1;
        *(uint2*)(outA + (size_t)qg * DIM + h * 32 + ch) = v;
    }
}

// ---------------------------------------------------------------------------
// Residual + LayerNorm: 4 rows/block, 64 threads/row, float4 I/O.
// ---------------------------------------------------------------------------
__global__ __launch_bounds__(256) void ln_kernel(
    const float* __restrict__ src, const float* __restrict__ y,
    const float* __restrict__ gamma, const float* __restrict__ beta,
    float* __restrict__ out)
{
    const unsigned FULL = 0xffffffffu;
    const int tid = threadIdx.x;
    const int r   = tid >> 6;          // 0..3 (row within block)
    const int t   = tid & 63;          // 0..63 (col/4)
    const int row = blockIdx.x * 4 + r;
    const size_t base = (size_t)row * DIM + t * 4;

    float4 a = *(const float4*)(src + base);
    float4 b = *(const float4*)(y + base);
    float4 x = make_float4(a.x + b.x, a.y + b.y, a.z + b.z, a.w + b.w);

    float s  = x.x + x.y + x.z + x.w;
    float s2 = x.x * x.x + x.y * x.y + x.z * x.z + x.w * x.w;
#pragma unroll
    for (int o = 16; o > 0; o >>= 1) {
        s  += __shfl_xor_sync(FULL, s, o);
        s2 += __shfl_xor_sync(FULL, s2, o);
    }
    __shared__ float ss[8], ss2[8];
    const int w = tid >> 5;
    if ((tid & 31) == 0) { ss[w] = s; ss2[w] = s2; }
    __syncthreads();
    const float sum  = ss[2 * r] + ss[2 * r + 1];
    const float sum2 = ss2[2 * r] + ss2[2 * r + 1];

    const float mu  = sum * (1.0f / DIM);
    const float var = sum2 * (1.0f / DIM) - mu * mu;
    const float rr = rsqrtf(var + 1e-5f);

    float4 g = *(const float4*)(gamma + t * 4);
    float4 be = *(const float4*)(beta + t * 4);
    float4 o;
    o.x = (x.x - mu) * rr * g.x + be.x;
    o.y = (x.y - mu) * rr * g.y + be.y;
    o.z = (x.z - mu) * rr * g.z + be.z;
    o.w = (x.w - mu) * rr * g.w + be.w;
    *(float4*)(out + base) = o;
}

// ---------------------------------------------------------------------------
extern "C" void kernel_launch(void* const* d_in, const int* in_sizes, int n_in,
                              void* d_out, int out_size)
{
    const float* src    = (const float*)d_in[0];
    const float* refpts = (const float*)d_in[1];
    const float* w_value = (const float*)d_in[4];
    const float* b_value = (const float*)d_in[5];
    const float* w_off   = (const float*)d_in[6];
    const float* b_off   = (const float*)d_in[7];
    const float* w_attn  = (const float*)d_in[8];
    const float* b_attn  = (const float*)d_in[9];
    const float* w_out   = (const float*)d_in[10];
    const float* b_out   = (const float*)d_in[11];
    const float* gamma   = (const float*)d_in[12];
    const float* beta    = (const float*)d_in[13];
    float* out = (float*)d_out;

    float *go, *ga, *g2;
    __half *gv2, *af, *bt;
    cudaGetSymbolAddress((void**)&gv2, g_value2);
    cudaGetSymbolAddress((void**)&go,  g_off);
    cudaGetSymbolAddress((void**)&ga,  g_attn);
    cudaGetSymbolAddress((void**)&g2,  g_out2);
    cudaGetSymbolAddress((void**)&af,  g_af);
    cudaGetSymbolAddress((void**)&bt,  g_btc);

    const int M = MROWS;
    cudaFuncSetAttribute(gemm1_kernel, cudaFuncAttributeMaxDynamicSharedMemorySize, SMEM1_BYTES);
    cudaFuncSetAttribute(gemm2_kernel, cudaFuncAttributeMaxDynamicSharedMemorySize, SMEM2_BYTES);

    dim3 blk(256);
    const int n4 = M * DIM / 4;
    const int gtiles = (M + 127) / 128;   // 192

    // fused weight transpose (smem tiles) + src -> fp16
    split_all_kernel<<<WT_TILES + (n4 + 255) / 256, blk>>>(
        src, af, n4, w_value, w_off, w_attn, w_out, bt);

    // fused input projections: N=640 as 5 x 128-wide tiles
    gemm1_kernel<<<dim3(gtiles, 5), blk, SMEM1_BYTES>>>(
        af, bt, gv2, go, ga, b_value, b_off, b_attn, M);

    // deformable sampling (dual-plane fp16 value; emits fp16 A into af)
    sample_kernel<<<MROWS, blk>>>(gv2, go, ga, refpts, af);

    // output projection: N=256 as 4 x 64-wide tiles, 3 CTAs/SM
    gemm2_kernel<<<dim3(gtiles, 4), blk, SMEM2_BYTES>>>(
        af, bt + 640 * 256, g2, b_out, M);

    // residual + layernorm (float4, 4 rows/block)
    ln_kernel<<<MROWS / 4, blk>>>(src, g2, gamma, beta, out);
}

// round 15
// speedup vs baseline: 1.1330x; 1.1330x over previous
#include <cuda_runtime.h>
#include <cuda_fp16.h>
#include <cstdint>
#include <math.h>

#define NB      2
#define LQ      12240
#define DIM     256
#define HEADS   8
#define LEVELS  4
#define POINTS  4
#define HD      32
#define MROWS   (NB * LQ)   // 24480

// ------------------------- scratch (no allocs allowed) ----------------------
// value in HEAD-MAJOR layout: [head][row][32 ch] fp16
__device__ __half g_value_h[HEADS * MROWS * HD];
__device__ float  g_off    [MROWS * DIM];
__device__ float  g_attn   [MROWS * HEADS * 16];
__device__ float  g_out2   [MROWS * DIM];

// fp16 A operand (src, then attention output) and concatenated transposed
// weights [n][k] K-major: rows 0-255 value, 256-511 off, 512-639 attn, 640-895 out
__device__ __half g_af [MROWS * DIM];
__device__ __half g_btc[896 * 256];

// ------------------------------ PTX helpers ---------------------------------
__device__ __forceinline__ uint32_t smem_u32(const void* p) {
    uint32_t a;
    asm("{ .reg .u64 t; cvta.to.shared.u64 t, %1; cvt.u32.u64 %0, t; }" : "=r"(a) : "l"(p));
    return a;
}
__device__ __forceinline__ void cpa16(uint32_t dst, const void* src, bool v) {
    asm volatile("cp.async.cg.shared.global [%0], [%1], 16, %2;"
        :: "r"(dst), "l"(src), "r"(v ? 16 : 0) : "memory");
}
__device__ __forceinline__ void ldsm_x4(uint32_t addr, uint32_t* r) {
    asm volatile("ldmatrix.sync.aligned.m8n8.x4.shared.b16 {%0,%1,%2,%3}, [%4];"
        : "=r"(r[0]), "=r"(r[1]), "=r"(r[2]), "=r"(r[3]) : "r"(addr));
}
__device__ __forceinline__ void mma_f16(float* c, const uint32_t* a, const uint32_t* b) {
    asm volatile("mma.sync.aligned.m16n8k16.row.col.f32.f16.f16.f32 "
        "{%0,%1,%2,%3}, {%4,%5,%6,%7}, {%8,%9}, {%0,%1,%2,%3};"
        : "+f"(c[0]), "+f"(c[1]), "+f"(c[2]), "+f"(c[3])
        : "r"(a[0]), "r"(a[1]), "r"(a[2]), "r"(a[3]), "r"(b[0]), "r"(b[1]));
}

// ---------------------------------------------------------------------------
// Fused split kernel:
//  blocks [0,224): 32x32 smem-tile transpose of the 4 weight matrices -> fp16
//  blocks [224,...): src fp32 -> fp16 (vectorized)
// ---------------------------------------------------------------------------
#define WT_TILES 224   // wv 64 | wo 64 | wa 32 | ww 64

__global__ __launch_bounds__(256) void split_all_kernel(
    const float* __restrict__ A, __half* __restrict__ Af, int n4,
    const float* __restrict__ wv, const float* __restrict__ wo,
    const float* __restrict__ wa, const float* __restrict__ ww,
    __half* __restrict__ Bt)
{
    const int bid = blockIdx.x;
    if (bid < WT_TILES) {
        __shared__ float sm[32][33];
        const float* src; int rowoff, Nc, local;
        if (bid < 64)       { src = wv; rowoff = 0;   Nc = 256; local = bid; }
        else if (bid < 128) { src = wo; rowoff = 256; Nc = 256; local = bid - 64; }
        else if (bid < 160) { src = wa; rowoff = 512; Nc = 128; local = bid - 128; }
        else                { src = ww; rowoff = 640; Nc = 256; local = bid - 160; }
        const int ntiles = Nc >> 5;
        const int k0 = (local / ntiles) * 32;
        const int n0 = (local % ntiles) * 32;
        const int tx = threadIdx.x & 31;
        const int ty = threadIdx.x >> 5;   // 0..7
#pragma unroll
        for (int i = 0; i < 4; i++)
            sm[ty + i * 8][tx] = src[(k0 + ty + i * 8) * Nc + n0 + tx];
        __syncthreads();
#pragma unroll
        for (int i = 0; i < 4; i++)
            Bt[(size_t)(rowoff + n0 + ty + i * 8) * 256 + k0 + tx] =
                __float2half_rn(sm[tx][ty + i * 8]);
    } else {
        int i = (bid - WT_TILES) * 256 + threadIdx.x;
        if (i >= n4) return;
        float4 a = ((const float4*)A)[i];
        __half2 p0 = __floats2half2_rn(a.x, a.y);
        __half2 p1 = __floats2half2_rn(a.z, a.w);
        uint2 v;
        v.x = *(uint32_t*)&p0;
        v.y = *(uint32_t*)&p1;
        *(uint2*)(Af + 4 * (size_t)i) = v;
    }
}

// ---------------------------------------------------------------------------
// GEMM1 (fused projections): CTA 128x128, 8 warps 4(M)x2(N), warp 32x64,
// 3-stage cp.async, 2 CTAs/SM. blockIdx.y 0-1 value(fp16 head-major),
// 2-3 off, 4 attn.
// ---------------------------------------------------------------------------
#define PADK 40
#define ST1_BYTES 20480     // A 10240 + B 10240
#define SMEM1_BYTES (3 * ST1_BYTES)

__global__ __launch_bounds__(256, 2) void gemm1_kernel(
    const __half* __restrict__ Af, const __half* __restrict__ Bt,
    __half* C0h, float* C1, float* C2,
    const float* b0, const float* b1, const float* b2, int M)
{
    extern __shared__ __align__(16) char smem[];
    const uint32_t sbase = smem_u32(smem);

    const int tid  = threadIdx.x;
    const int lane = tid & 31;
    const int wid  = tid >> 5;
    const int wm   = wid & 3;
    const int wn   = wid >> 2;
    const int bm   = blockIdx.x * 128;
    const int bn   = blockIdx.y * 128;

    float* Cp; const float* bp; int stride, coloff; bool halfOut = false;
    if (blockIdx.y < 2)      { Cp = nullptr; bp = b0; stride = 256; coloff = bn; halfOut = true; }
    else if (blockIdx.y < 4) { Cp = C1; bp = b1; stride = 256; coloff = bn - 256; }
    else                     { Cp = C2; bp = b2; stride = 128; coloff = 0; }

    float acc[2][8][4];
#pragma unroll
    for (int i = 0; i < 2; i++)
#pragma unroll
        for (int j = 0; j < 8; j++)
#pragma unroll
            for (int t = 0; t < 4; t++) acc[i][j][t] = 0.f;

    auto load_chunk = [&](int kk, int st) {
        const uint32_t base = sbase + st * ST1_BYTES;
#pragma unroll
        for (int t = 0; t < 2; t++) {
            int idx = tid + 256 * t;
            int row = idx >> 2, seg = idx & 3;
            uint32_t d = (uint32_t)(row * PADK + seg * 8) * 2;
            bool va = (bm + row) < M;
            cpa16(base + d, Af + (size_t)(bm + row) * 256 + kk * 32 + seg * 8, va);
            cpa16(base + 10240 + d, Bt + (size_t)(bn + row) * 256 + kk * 32 + seg * 8, true);
        }
        asm volatile("cp.async.commit_group;" ::: "memory");
    };

    load_chunk(0, 0);
    load_chunk(1, 1);

    const int arow = wm * 32 + (lane & 15);
    const int acolbase = (lane >> 4) * 8;
    const int browq = wn * 64 + (lane & 7) + ((lane >> 4) & 1) * 8;
    const int bcolbase = ((lane >> 3) & 1) * 8;

    for (int kk = 0; kk < 8; kk++) {
        asm volatile("cp.async.wait_group 1;" ::: "memory");
        __syncthreads();
        if (kk + 2 < 8) load_chunk(kk + 2, (kk + 2) % 3);

        const uint32_t ab = sbase + (kk % 3) * ST1_BYTES;

        uint32_t Ar[2][2][4];
        uint32_t Br[2][4][4];
#pragma unroll
        for (int ks = 0; ks < 2; ks++) {
#pragma unroll
            for (int mt = 0; mt < 2; mt++) {
                int row = arow + mt * 16;
                int col = ks * 16 + acolbase;
                ldsm_x4(ab + (uint32_t)(row * PADK + col) * 2, Ar[ks][mt]);
            }
#pragma unroll
            for (int q = 0; q < 4; q++) {
                int rowB = browq + q * 16;
                int colB = bcolbase + ks * 16;
                ldsm_x4(ab + 10240 + (uint32_t)(rowB * PADK + colB) * 2, Br[ks][q]);
            }
        }
#pragma unroll
        for (int ks = 0; ks < 2; ks++)
#pragma unroll
            for (int q = 0; q < 4; q++)
#pragma unroll
                for (int mt = 0; mt < 2; mt++) {
                    mma_f16(acc[mt][2 * q + 0], Ar[ks][mt], Br[ks][q] + 0);
                    mma_f16(acc[mt][2 * q + 1], Ar[ks][mt], Br[ks][q] + 2);
                }
    }

#pragma unroll
    for (int mt = 0; mt < 2; mt++) {
        int r0 = bm + wm * 32 + mt * 16 + (lane >> 2);
        int r1 = r0 + 8;
#pragma unroll
        for (int nt = 0; nt < 8; nt++) {
            int c = coloff + wn * 64 + nt * 8 + 2 * (lane & 3);
            float bb0 = bp[c], bb1 = bp[c + 1];
            if (halfOut) {
                const int h = c >> 5, chm = c & 31;
                __half* basep = C0h + (size_t)h * MROWS * HD + chm;
                if (r0 < M)
                    *(__half2*)(basep + (size_t)r0 * HD) =
                        __floats2half2_rn(acc[mt][nt][0] + bb0, acc[mt][nt][1] + bb1);
                if (r1 < M)
                    *(__half2*)(basep + (size_t)r1 * HD) =
                        __floats2half2_rn(acc[mt][nt][2] + bb0, acc[mt][nt][3] + bb1);
            } else {
                if (r0 < M) {
                    float2 v = make_float2(acc[mt][nt][0] + bb0, acc[mt][nt][1] + bb1);
                    *(float2*)&Cp[(size_t)r0 * stride + c] = v;
                }
                if (r1 < M) {
                    float2 v = make_float2(acc[mt][nt][2] + bb0, acc[mt][nt][3] + bb1);
                    *(float2*)&Cp[(size_t)r1 * stride + c] = v;
                }
            }
        }
    }
}

// ---------------------------------------------------------------------------
// GEMM2 (output projection): CTA 128x64, 8 warps 4(M)x2(N), warp 32x32,
// 3-stage cp.async, 3 CTAs/SM.
// ---------------------------------------------------------------------------
#define A2_BYTES 10240
#define B2_BYTES 5120
#define ST2_BYTES (A2_BYTES + B2_BYTES)
#define SMEM2_BYTES (3 * ST2_BYTES)

__global__ __launch_bounds__(256, 3) void gemm2_kernel(
    const __half* __restrict__ Af, const __half* __restrict__ Bt,
    float* C, const float* bias, int M)
{
    extern __shared__ __align__(16) char smem[];
    const uint32_t sbase = smem_u32(smem);

    const int tid  = threadIdx.x;
    const int lane = tid & 31;
    const int wid  = tid >> 5;
    const int wm   = wid & 3;
    const int wn   = wid >> 2;
    const int bm   = blockIdx.x * 128;
    const int bn   = blockIdx.y * 64;

    float acc[2][4][4];
#pragma unroll
    for (int i = 0; i < 2; i++)
#pragma unroll
        for (int j = 0; j < 4; j++)
#pragma unroll
            for (int t = 0; t < 4; t++) acc[i][j][t] = 0.f;

    auto load_chunk = [&](int kk, int st) {
        const uint32_t base = sbase + st * ST2_BYTES;
#pragma unroll
        for (int t = 0; t < 2; t++) {
            int idx = tid + 256 * t;
            int row = idx >> 2, seg = idx & 3;
            uint32_t d = (uint32_t)(row * PADK + seg * 8) * 2;
            bool va = (bm + row) < M;
            cpa16(base + d, Af + (size_t)(bm + row) * 256 + kk * 32 + seg * 8, va);
        }
        {
            int row = tid >> 2, seg = tid & 3;
            uint32_t d = (uint32_t)(row * PADK + seg * 8) * 2;
            cpa16(base + A2_BYTES + d, Bt + (size_t)(bn + row) * 256 + kk * 32 + seg * 8, true);
        }
        asm volatile("cp.async.commit_group;" ::: "memory");
    };

    load_chunk(0, 0);
    load_chunk(1, 1);

    const int arow = wm * 32 + (lane & 15);
    const int acolbase = (lane >> 4) * 8;
    const int browq = wn * 32 + (lane & 7) + ((lane >> 4) & 1) * 8;
    const int bcolbase = ((lane >> 3) & 1) * 8;

    for (int kk = 0; kk < 8; kk++) {
        asm volatile("cp.async.wait_group 1;" ::: "memory");
        __syncthreads();
        if (kk + 2 < 8) load_chunk(kk + 2, (kk + 2) % 3);

        const uint32_t ab = sbase + (kk % 3) * ST2_BYTES;

        uint32_t Ar[2][2][4];
        uint32_t Br[2][2][4];
#pragma unroll
        for (int ks = 0; ks < 2; ks++) {
#pragma unroll
            for (int mt = 0; mt < 2; mt++) {
                int row = arow + mt * 16;
                int col = ks * 16 + acolbase;
                ldsm_x4(ab + (uint32_t)(row * PADK + col) * 2, Ar[ks][mt]);
            }
#pragma unroll
            for (int q = 0; q < 2; q++) {
                int rowB = browq + q * 16;
                int colB = bcolbase + ks * 16;
                ldsm_x4(ab + A2_BYTES + (uint32_t)(rowB * PADK + colB) * 2, Br[ks][q]);
            }
        }
#pragma unroll
        for (int ks = 0; ks < 2; ks++)
#pragma unroll
            for (int q = 0; q < 2; q++)
#pragma unroll
                for (int mt = 0; mt < 2; mt++) {
                    mma_f16(acc[mt][2 * q + 0], Ar[ks][mt], Br[ks][q] + 0);
                    mma_f16(acc[mt][2 * q + 1], Ar[ks][mt], Br[ks][q] + 2);
                }
    }

#pragma unroll
    for (int mt = 0; mt < 2; mt++) {
        int r0 = bm + wm * 32 + mt * 16 + (lane >> 2);
        int r1 = r0 + 8;
#pragma unroll
        for (int nt = 0; nt < 4; nt++) {
            int c = bn + wn * 32 + nt * 8 + 2 * (lane & 3);
            float bb0 = bias[c], bb1 = bias[c + 1];
            if (r0 < M) {
                float2 v = make_float2(acc[mt][nt][0] + bb0, acc[mt][nt][1] + bb1);
                *(float2*)&C[(size_t)r0 * 256 + c] = v;
            }
            if (r1 < M) {
                float2 v = make_float2(acc[mt][nt][2] + bb0, acc[mt][nt][3] + bb1);
                *(float2*)&C[(size_t)r1 * 256 + c] = v;
            }
        }
    }
}

// ---------------------------------------------------------------------------
// Deformable sampling: block = 2 QUERIES. Prep uses all 256 threads
// (tid>>7 = query, tid&127 = head*16+point). Gather: warp = head, each warp
// processes BOTH queries per iteration -> 2 independent load chains (2x MLP).
// Epilogue: lanes 0-7 write query0, lanes 8-15 write query1.
// ---------------------------------------------------------------------------
__global__ __launch_bounds__(256) void sample_kernel(
    const __half* __restrict__ value,
    const float* __restrict__ off,
    const float* __restrict__ logits,
    const float* __restrict__ ref,
    __half* __restrict__ outA)
{
    const unsigned FULL = 0xffffffffu;
    __shared__ float2 s_aw[2 * HEADS * 16 * 4];   // [query][(h*16+p)*4+slot]

    const int qg0 = blockIdx.x * 2;               // LQ even -> pair same batch
    const int n   = qg0 / LQ;
    const int tid = threadIdx.x;

    {
        const int q  = tid >> 7;          // 0/1
        const int qg = qg0 + q;
        const int hp = tid & 127;
        const int h  = hp >> 4;
        const int p  = hp & 15;
        const int l  = p >> 2;

        float lg = logits[(size_t)qg * 128 + h * 16 + p];
        float mx = lg;
#pragma unroll
        for (int o = 8; o > 0; o >>= 1) mx = fmaxf(mx, __shfl_xor_sync(FULL, mx, o));
        float e = __expf(lg - mx);
        float sum = e;
#pragma unroll
        for (int o = 8; o > 0; o >>= 1) sum += __shfl_xor_sync(FULL, sum, o);
        const float aw = __fdividef(e, sum);

        const int W  = 96 >> l;
        const int S0 = 12288 - 3 * (4096 >> (2 * l));
        const float rx = ref[(size_t)qg * (LEVELS * 2) + l * 2 + 0] * (float)W;
        const float ry = ref[(size_t)qg * (LEVELS * 2) + l * 2 + 1] * (float)W;
        const float ox = off[(size_t)qg * DIM + h * 32 + p * 2 + 0];
        const float oy = off[(size_t)qg * DIM + h * 32 + p * 2 + 1];
        const float x = rx + ox - 0.5f;
        const float y = ry + oy - 0.5f;
        const float x0f = floorf(x), y0f = floorf(y);
        const int x0 = (int)x0f, y0 = (int)y0f;
        const int x1 = x0 + 1, y1 = y0 + 1;
        const float fx = x - x0f, fy = y - y0f;

        const float wx0 = (x0 >= 0 && x0 < W) ? (1.f - fx) : 0.f;
        const float wx1 = (x1 >= 0 && x1 < W) ? fx : 0.f;
        const int pb = min(max(x0, 0), W - 2);
        const float wa = (pb == x0) ? wx0 : ((pb == x1) ? wx1 : 0.f);
        const float wb = (pb + 1 == x0) ? wx0 : ((pb + 1 == x1) ? wx1 : 0.f);
        const float wy0 = ((y0 >= 0 && y0 < W) ? (1.f - fy) : 0.f) * aw;
        const float wy1 = ((y1 >= 0 && y1 < W) ? fy : 0.f) * aw;
        const int y0c = min(max(y0, 0), W - 1);
        const int y1c = min(max(y1, 0), W - 1);
        const int a0 = (S0 + y0c * W + pb) * HD;
        const int a1 = (S0 + y1c * W + pb) * HD;

        const int b = tid * 4;
        s_aw[b + 0] = make_float2(__int_as_float(a0),      wa * wy0);
        s_aw[b + 1] = make_float2(__int_as_float(a0 + HD), wb * wy0);
        s_aw[b + 2] = make_float2(__int_as_float(a1),      wa * wy1);
        s_aw[b + 3] = make_float2(__int_as_float(a1 + HD), wb * wy1);
    }
    __syncthreads();

    const int h    = tid >> 5;
    const int lane = tid & 31;
    const int slot = lane >> 3;        // (ypair<<1)|xslot
    const int ch   = (lane & 7) * 4;   // channel base 0..28

    const __half* vb = value + ((size_t)h * MROWS + (size_t)n * LQ) * HD + ch;
    const int si = (h * 16) * 4 + slot;
    float4 acc0 = make_float4(0.f, 0.f, 0.f, 0.f);
    float4 acc1 = acc0;
#pragma unroll
    for (int p = 0; p < 16; p++) {
        const float2 t0 = s_aw[si + p * 4];
        const float2 t1 = s_aw[512 + si + p * 4];
        const uint2 raw0 = *(const uint2*)(vb + __float_as_int(t0.x));
        const uint2 raw1 = *(const uint2*)(vb + __float_as_int(t1.x));
        const float w0 = t0.y, w1 = t1.y;
        const float2 u00 = __half22float2(*(const __half2*)&raw0.x);
        const float2 u01 = __half22float2(*(const __half2*)&raw0.y);
        const float2 u10 = __half22float2(*(const __half2*)&raw1.x);
        const float2 u11 = __half22float2(*(const __half2*)&raw1.y);
        acc0.x = fmaf(w0, u00.x, acc0.x);
        acc0.y = fmaf(w0, u00.y, acc0.y);
        acc0.z = fmaf(w0, u01.x, acc0.z);
        acc0.w = fmaf(w0, u01.y, acc0.w);
        acc1.x = fmaf(w1, u10.x, acc1.x);
        acc1.y = fmaf(w1, u10.y, acc1.y);
        acc1.z = fmaf(w1, u11.x, acc1.z);
        acc1.w = fmaf(w1, u11.y, acc1.w);
    }
#pragma unroll
    for (int o = 8; o <= 16; o <<= 1) {
        acc0.x += __shfl_xor_sync(FULL, acc0.x, o);
        acc0.y += __shfl_xor_sync(FULL, acc0.y, o);
        acc0.z += __shfl_xor_sync(FULL, acc0.z, o);
        acc0.w += __shfl_xor_sync(FULL, acc0.w, o);
        acc1.x += __shfl_xor_sync(FULL, acc1.x, o);
        acc1.y += __shfl_xor_sync(FULL, acc1.y, o);
        acc1.z += __shfl_xor_sync(FULL, acc1.z, o);
        acc1.w += __shfl_xor_sync(FULL, acc1.w, o);
    }
    if (lane < 16) {
        const int q = lane >> 3;                 // 0: query0, 1: query1
        const float4 a = q ? acc1 : acc0;
        __half2 p0 = __floats2half2_rn(a.x, a.y);
        __half2 p1 = __floats2half2_rn(a.z, a.w);
        uint2 v;
        v.x = *(uint32_t*)&p0;
        v.y = *(uint32_t*)&p1;
        *(uint2*)(outA + (size_t)(qg0 + q) * DIM + h * 32 + ch) = v;
    }
}

// ---------------------------------------------------------------------------
// Residual + LayerNorm: 4 rows/block, 64 threads/row, float4 I/O.
// ---------------------------------------------------------------------------
__global__ __launch_bounds__(256) void ln_kernel(
    const float* __restrict__ src, const float* __restrict__ y,
    const float* __restrict__ gamma, const float* __restrict__ beta,
    float* __restrict__ out)
{
    const unsigned FULL = 0xffffffffu;
    const int tid = threadIdx.x;
    const int r   = tid >> 6;          // 0..3 (row within block)
    const int t   = tid & 63;          // 0..63 (col/4)
    const int row = blockIdx.x * 4 + r;
    const size_t base = (size_t)row * DIM + t * 4;

    float4 a = *(const float4*)(src + base);
    float4 b = *(const float4*)(y + base);
    float4 x = make_float4(a.x + b.x, a.y + b.y, a.z + b.z, a.w + b.w);

    float s  = x.x + x.y + x.z + x.w;
    float s2 = x.x * x.x + x.y * x.y + x.z * x.z + x.w * x.w;
#pragma unroll
    for (int o = 16; o > 0; o >>= 1) {
        s  += __shfl_xor_sync(FULL, s, o);
        s2 += __shfl_xor_sync(FULL, s2, o);
    }
    __shared__ float ss[8], ss2[8];
    const int w = tid >> 5;
    if ((tid & 31) == 0) { ss[w] = s; ss2[w] = s2; }
    __syncthreads();
    const float sum  = ss[2 * r] + ss[2 * r + 1];
    const float sum2 = ss2[2 * r] + ss2[2 * r + 1];

    const float mu  = sum * (1.0f / DIM);
    const float var = sum2 * (1.0f / DIM) - mu * mu;
    const float rr = rsqrtf(var + 1e-5f);

    float4 g = *(const float4*)(gamma + t * 4);
    float4 be = *(const float4*)(beta + t * 4);
    float4 o;
    o.x = (x.x - mu) * rr * g.x + be.x;
    o.y = (x.y - mu) * rr * g.y + be.y;
    o.z = (x.z - mu) * rr * g.z + be.z;
    o.w = (x.w - mu) * rr * g.w + be.w;
    *(float4*)(out + base) = o;
}

// ---------------------------------------------------------------------------
extern "C" void kernel_launch(void* const* d_in, const int* in_sizes, int n_in,
                              void* d_out, int out_size)
{
    const float* src    = (const float*)d_in[0];
    const float* refpts = (const float*)d_in[1];
    const float* w_value = (const float*)d_in[4];
    const float* b_value = (const float*)d_in[5];
    const float* w_off   = (const float*)d_in[6];
    const float* b_off   = (const float*)d_in[7];
    const float* w_attn  = (const float*)d_in[8];
    const float* b_attn  = (const float*)d_in[9];
    const float* w_out   = (const float*)d_in[10];
    const float* b_out   = (const float*)d_in[11];
    const float* gamma   = (const float*)d_in[12];
    const float* beta    = (const float*)d_in[13];
    float* out = (float*)d_out;

    float *go, *ga, *g2;
    __half *gvh, *af, *bt;
    cudaGetSymbolAddress((void**)&gvh, g_value_h);
    cudaGetSymbolAddress((void**)&go,  g_off);
    cudaGetSymbolAddress((void**)&ga,  g_attn);
    cudaGetSymbolAddress((void**)&g2,  g_out2);
    cudaGetSymbolAddress((void**)&af,  g_af);
    cudaGetSymbolAddress((void**)&bt,  g_btc);

    const int M = MROWS;
    cudaFuncSetAttribute(gemm1_kernel, cudaFuncAttributeMaxDynamicSharedMemorySize, SMEM1_BYTES);
    cudaFuncSetAttribute(gemm2_kernel, cudaFuncAttributeMaxDynamicSharedMemorySize, SMEM2_BYTES);

    dim3 blk(256);
    const int n4 = M * DIM / 4;
    const int gtiles = (M + 127) / 128;   // 192

    // fused weight transpose (smem tiles) + src -> fp16
    split_all_kernel<<<WT_TILES + (n4 + 255) / 256, blk>>>(
        src, af, n4, w_value, w_off, w_attn, w_out, bt);

    // fused input projections: N=640 as 5 x 128-wide tiles
    gemm1_kernel<<<dim3(gtiles, 5), blk, SMEM1_BYTES>>>(
        af, bt, gvh, go, ga, b_value, b_off, b_attn, M);

    // deformable sampling: 2 queries per block
    sample_kernel<<<MROWS / 2, blk>>>(gvh, go, ga, refpts, af);

    // output projection: N=256 as 4 x 64-wide tiles, 3 CTAs/SM
    gemm2_kernel<<<dim3(gtiles, 4), blk, SMEM2_BYTES>>>(
        af, bt + 640 * 256, g2, b_out, M);

    // residual + layernorm (float4, 4 rows/block)
    ln_kernel<<<MROWS / 4, blk>>>(src, g2, gamma, beta, out);
}